// round 12
// baseline (speedup 1.0000x reference)
#include <cuda_runtime.h>
#include <cstdint>

#define NUM_TYPES 8
#define NBLK 148
#define NTHR 512
#define NWARP 16
#define IDX_CAP 352
#define MAX_TILES 24

// ---- dynamic smem byte offsets ----
#define SW_OFF   0          // 131072 : W0 fp32 raw, [t][k][n ^ 8*(k&7)]
#define SQ_OFF   131072     // 94720  : sorted Q chunk, 370 rows x 64 f32, XOR-swizzled
#define B0_OFF   225792     // 2048
#define W1_OFF   227840     // 2048
#define IDX_OFF  229888     // 384*4 = 1536
#define HIST_OFF 231424
#define BASE_OFF 231456
#define OFF_OFF  231488
#define TZ_OFF   231520
#define TS_OFF   231616
#define TL_OFF   231712
#define NT_OFF   231808
#define SMEM_BYTES 231936

__device__ __forceinline__ uint32_t smem_u32(const void* p) {
    uint32_t a;
    asm("{ .reg .u64 t; cvta.to.shared.u64 t, %1; cvt.u32.u64 %0, t; }" : "=r"(a) : "l"(p));
    return a;
}
__device__ __forceinline__ uint32_t f2tf(float x) {
    uint32_t r; asm("cvt.rna.tf32.f32 %0, %1;" : "=r"(r) : "f"(x)); return r;
}
__device__ __forceinline__ float fast_tanh(float x) {
    float r; asm("tanh.approx.f32 %0, %1;" : "=f"(r) : "f"(x)); return r;
}
__device__ __forceinline__ void cpa16(uint32_t dst, const void* src) {
    asm volatile("cp.async.cg.shared.global [%0], [%1], 16;"
                 :: "r"(dst), "l"(src) : "memory");
}
__device__ __forceinline__ void cpa_commit() {
    asm volatile("cp.async.commit_group;" ::: "memory");
}
__device__ __forceinline__ void cpa_wait0() {
    asm volatile("cp.async.wait_group 0;" ::: "memory");
}
__device__ __forceinline__ void mma8(float* c, const uint32_t* a,
                                     uint32_t b0, uint32_t b1) {
    asm volatile("mma.sync.aligned.m16n8k8.row.col.f32.tf32.tf32.f32 "
        "{%0,%1,%2,%3}, {%4,%5,%6,%7}, {%8,%9}, {%0,%1,%2,%3};"
        : "+f"(c[0]), "+f"(c[1]), "+f"(c[2]), "+f"(c[3])
        : "r"(a[0]), "r"(a[1]), "r"(a[2]), "r"(a[3]), "r"(b0), "r"(b1));
}

// ---------------- init: out = N * b1 (un-poisons d_out) ----------------
__global__ void tnep_init_kernel(float* __restrict__ out,
                                 const float* __restrict__ b1, int n) {
    out[0] = b1[0] * (float)n;
}

__global__ __launch_bounds__(NTHR, 1)
void tnep_mma(const float* __restrict__ q,
              const float* __restrict__ W0,
              const float* __restrict__ b0,
              const float* __restrict__ W1,
              const int*   __restrict__ Z,
              float* __restrict__ out,
              int n, int per)
{
    extern __shared__ char smc[];
    uint32_t* sW  = (uint32_t*)(smc + SW_OFF);   // raw fp32 weights, swizzled
    uint32_t* sQ  = (uint32_t*)(smc + SQ_OFF);   // sorted Q rows, swizzled
    float* sB0 = (float*)(smc + B0_OFF);
    float* sW1 = (float*)(smc + W1_OFF);
    int* sIdx = (int*)(smc + IDX_OFF);
    int* hist = (int*)(smc + HIST_OFF);
    int* bse  = (int*)(smc + BASE_OFF);
    int* off  = (int*)(smc + OFF_OFF);
    int* tZ   = (int*)(smc + TZ_OFF);
    int* tS   = (int*)(smc + TS_OFF);
    int* tL   = (int*)(smc + TL_OFF);
    int* nT   = (int*)(smc + NT_OFF);

    const uint32_t smb = smem_u32(smc);
    const int tid  = threadIdx.x;
    const int wid  = tid >> 5;
    const int lane = tid & 31;

    // ---- issue weight copies ASYNC (hidden behind the sort below) ----
    #pragma unroll
    for (int it = 0; it < 16; ++it) {                   // 8192 float4 / 512 thr
        const int i = tid + it * NTHR;
        const int t = i >> 10, j = i & 1023;
        const int d = j >> 4, n4 = j & 15;
        const uint32_t dst = smb + SW_OFF +
            (uint32_t)(t * 4096 + d * 64 + 4 * (n4 ^ (2 * (d & 7)))) * 4;
        cpa16(dst, (const float4*)W0 + i);
    }
    if (tid < 128) {
        cpa16(smb + B0_OFF + tid * 16, (const float4*)b0 + tid);
        cpa16(smb + W1_OFF + tid * 16, (const float4*)W1 + tid);
    }
    cpa_commit();

    for (int i = tid; i < IDX_CAP + 32; i += NTHR) sIdx[i] = 0;
    if (tid < NUM_TYPES) hist[tid] = 0;
    __syncthreads();

    // ---- local counting sort by type (overlaps weight cp.async) ----
    const int s   = blockIdx.x * per;
    const int cnt = max(0, min(n - s, per));
    const int cnt_pad = (cnt + 31) & ~31;

    for (int i = tid; i < cnt_pad; i += NTHR) {
        const bool v = (i < cnt);
        const int  z = v ? Z[s + i] : -1;
        const unsigned m = __match_any_sync(0xffffffffu, z);
        if (v && (lane == (__ffs(m) - 1)))
            atomicAdd(&hist[z], __popc(m));
    }
    __syncthreads();
    if (tid == 0) {
        int acc = 0, nt = 0;
        #pragma unroll
        for (int t = 0; t < NUM_TYPES; ++t) { bse[t] = acc; off[t] = acc; acc += hist[t]; }
        for (int t = 0; t < NUM_TYPES; ++t) {
            int c = hist[t], st = bse[t];
            while (c > 0 && nt < MAX_TILES) {
                tZ[nt] = t; tS[nt] = st; tL[nt] = min(32, c);
                st += 32; c -= 32; ++nt;
            }
        }
        nT[0] = nt;
    }
    __syncthreads();
    for (int i = tid; i < cnt_pad; i += NTHR) {
        const bool v = (i < cnt);
        const int  z = v ? Z[s + i] : -1;
        const unsigned m = __match_any_sync(0xffffffffu, z);
        const int leader = __ffs(m) - 1;
        const int rank   = __popc(m & ((1u << lane) - 1));
        int p0 = 0;
        if (v && lane == leader) p0 = atomicAdd(&off[z], __popc(m));
        p0 = __shfl_sync(0xffffffffu, p0, leader);
        if (v) sIdx[p0 + rank] = s + i;
    }
    __syncthreads();

    // ---- stage the ENTIRE sorted Q chunk via cp.async (one shot) ----
    // row r (sorted order), float4 col sc4 -> dst col4 = sc4 ^ (r&7)
    {
        const int nf4 = cnt_pad * 16;
        for (int j = tid; j < nf4; j += NTHR) {
            const int r = j >> 4, sc4 = j & 15;
            const int gidx = sIdx[r];
            const uint32_t dst = smb + SQ_OFF +
                (uint32_t)(r * 64 + 4 * (sc4 ^ (r & 7))) * 4;
            cpa16(dst, q + (size_t)gidx * 64 + 4 * sc4);
        }
    }
    cpa_commit();
    cpa_wait0();          // weights + Q all resident now
    __syncthreads();

    // ---- MMA mainloop: one warp per 32-atom type-pure tile; NO memory waits ----
    const int ntiles = nT[0];
    const int g  = lane >> 2;       // 0..7
    const int t4 = lane & 3;        // 0..3
    float esum = 0.0f;

    for (int ti = wid; ti < ntiles; ti += NWARP) {
        const int z   = tZ[ti];
        const int ts  = tS[ti];
        const int len = tL[ti];

        float C[8][8];
        #pragma unroll
        for (int i = 0; i < 8; ++i)
            #pragma unroll
            for (int j = 0; j < 8; ++j) C[i][j] = 0.0f;

        const uint32_t* wz = sW + z * 4096;
        const int rbase = ts + g;
        // rows rbase, rbase+8, rbase+16, rbase+24 share (row&7) -> one swizzle const
        const int kx = 4 * (rbase & 7);
        const uint32_t* r0 = sQ + (rbase     ) * 64;
        const uint32_t* r1 = sQ + (rbase +  8) * 64;
        const uint32_t* r2 = sQ + (rbase + 16) * 64;
        const uint32_t* r3 = sQ + (rbase + 24) * 64;

        #pragma unroll
        for (int kc = 0; kc < 8; ++kc) {
            const int k0 = (8 * kc + t4) ^ kx;
            const int k4 = (8 * kc + t4 + 4) ^ kx;

            // A fragments: raw fp32 -> hi (rna tf32) + lo residual (conflict-free LDS)
            uint32_t a0h[4], a0l[4], a1h[4], a1l[4];
            {
                const float x0 = __uint_as_float(r0[k0]);
                const float x1 = __uint_as_float(r1[k0]);
                const float x2 = __uint_as_float(r0[k4]);
                const float x3 = __uint_as_float(r1[k4]);
                a0h[0] = f2tf(x0); a0l[0] = __float_as_uint(x0 - __uint_as_float(a0h[0]));
                a0h[1] = f2tf(x1); a0l[1] = __float_as_uint(x1 - __uint_as_float(a0h[1]));
                a0h[2] = f2tf(x2); a0l[2] = __float_as_uint(x2 - __uint_as_float(a0h[2]));
                a0h[3] = f2tf(x3); a0l[3] = __float_as_uint(x3 - __uint_as_float(a0h[3]));
            }
            {
                const float x0 = __uint_as_float(r2[k0]);
                const float x1 = __uint_as_float(r3[k0]);
                const float x2 = __uint_as_float(r2[k4]);
                const float x3 = __uint_as_float(r3[k4]);
                a1h[0] = f2tf(x0); a1l[0] = __float_as_uint(x0 - __uint_as_float(a1h[0]));
                a1h[1] = f2tf(x1); a1l[1] = __float_as_uint(x1 - __uint_as_float(a1h[1]));
                a1h[2] = f2tf(x2); a1l[2] = __float_as_uint(x2 - __uint_as_float(a1h[2]));
                a1h[3] = f2tf(x3); a1l[3] = __float_as_uint(x3 - __uint_as_float(a1h[3]));
            }

            // B fragments: raw fp32 (HW tf32 truncation), swizzled conflict-free
            const int kb0 = 8 * kc + t4, kb1 = kb0 + 4;
            const uint32_t* wr0 = wz + kb0 * 64;
            const uint32_t* wr1 = wz + kb1 * 64;
            const int sx0 = 8 * (kb0 & 7);
            const int sx1 = 8 * (kb1 & 7);
            #pragma unroll
            for (int nt = 0; nt < 8; ++nt) {
                const int nn = 8 * nt + g;
                const uint32_t bf0 = wr0[nn ^ sx0];
                const uint32_t bf1 = wr1[nn ^ sx1];
                mma8(C[nt],     a0h, bf0, bf1);
                mma8(C[nt],     a0l, bf0, bf1);
                mma8(C[nt] + 4, a1h, bf0, bf1);
                mma8(C[nt] + 4, a1l, bf0, bf1);
            }
        }

        // epilogue: bias + tanh + dot W1, mask padded rows
        const float* zb = sB0 + z * 64;
        const float* zw = sW1 + z * 64;
        const bool v0 = (g      < len), v1 = (g + 8  < len);
        const bool v2 = (g + 16 < len), v3 = (g + 24 < len);
        #pragma unroll
        for (int nt = 0; nt < 8; ++nt) {
            const int n0 = nt * 8 + 2 * t4, n1 = n0 + 1;
            const float bb0 = zb[n0], bb1 = zb[n1];
            const float ww0 = zw[n0], ww1 = zw[n1];
            if (v0) esum += fast_tanh(C[nt][0] + bb0) * ww0
                          + fast_tanh(C[nt][1] + bb1) * ww1;
            if (v1) esum += fast_tanh(C[nt][2] + bb0) * ww0
                          + fast_tanh(C[nt][3] + bb1) * ww1;
            if (v2) esum += fast_tanh(C[nt][4] + bb0) * ww0
                          + fast_tanh(C[nt][5] + bb1) * ww1;
            if (v3) esum += fast_tanh(C[nt][6] + bb0) * ww0
                          + fast_tanh(C[nt][7] + bb1) * ww1;
        }
    }

    // ---- reduce + one atomic per warp ----
    #pragma unroll
    for (int o = 16; o > 0; o >>= 1)
        esum += __shfl_xor_sync(0xffffffffu, esum, o);
    if (lane == 0)
        atomicAdd(out, esum);
}

extern "C" void kernel_launch(void* const* d_in, const int* in_sizes, int n_in,
                              void* d_out, int out_size) {
    // metadata order: descriptors, W0, b0, W1, b1, Z
    const float* q  = (const float*)d_in[0];
    const float* W0 = (const float*)d_in[1];
    const float* b0 = (const float*)d_in[2];
    const float* W1 = (const float*)d_in[3];
    const float* b1 = (const float*)d_in[4];
    const int*   Z  = (const int*)  d_in[5];
    float* out = (float*)d_out;

    const int n = in_sizes[5];            // N_ATOMS
    int per = (n + NBLK - 1) / NBLK;
    if (per > IDX_CAP) per = IDX_CAP;     // 148*352 = 52096 >= 50000

    cudaFuncSetAttribute(tnep_mma,
                         cudaFuncAttributeMaxDynamicSharedMemorySize,
                         SMEM_BYTES);

    tnep_init_kernel<<<1, 1>>>(out, b1, n);
    tnep_mma<<<NBLK, NTHR, SMEM_BYTES>>>(q, W0, b0, W1, Z, out, n, per);
}

// round 13
// speedup vs baseline: 1.1592x; 1.1592x over previous
#include <cuda_runtime.h>
#include <cstdint>

#define NUM_TYPES 8
#define NBLK 148
#define NTHR 512
#define NWARP 16
#define IDX_CAP 352
#define MAX_TASKS 32

// ---- dynamic smem byte offsets ----
#define SW_OFF   0          // 131072 : W0 fp32 raw, [t][k][n ^ 8*(k&7)]
#define SQ_OFF   131072     // 90112  : Q chunk (original order), row-swizzled
#define B0_OFF   221184     // 2048
#define W1_OFF   223232     // 2048
#define IDX_OFF  225280     // 384*4
#define SZ_OFF   226816     // 352*4 (+pad)
#define HIST_OFF 228352
#define BASE_OFF 228384
#define OFF_OFF  228416
#define TZ_OFF   228448
#define TS_OFF   228576
#define TL_OFF   228704
#define NT_OFF   228832
#define SMEM_BYTES 228864

__device__ __forceinline__ uint32_t smem_u32(const void* p) {
    uint32_t a;
    asm("{ .reg .u64 t; cvta.to.shared.u64 t, %1; cvt.u32.u64 %0, t; }" : "=r"(a) : "l"(p));
    return a;
}
__device__ __forceinline__ uint32_t f2tf(float x) {
    uint32_t r; asm("cvt.rna.tf32.f32 %0, %1;" : "=r"(r) : "f"(x)); return r;
}
__device__ __forceinline__ float fast_tanh(float x) {
    float r; asm("tanh.approx.f32 %0, %1;" : "=f"(r) : "f"(x)); return r;
}
__device__ __forceinline__ void cpa16(uint32_t dst, const void* src) {
    asm volatile("cp.async.cg.shared.global [%0], [%1], 16;"
                 :: "r"(dst), "l"(src) : "memory");
}
__device__ __forceinline__ void cpa4(uint32_t dst, const void* src) {
    asm volatile("cp.async.ca.shared.global [%0], [%1], 4;"
                 :: "r"(dst), "l"(src) : "memory");
}
__device__ __forceinline__ void cpa_commit() {
    asm volatile("cp.async.commit_group;" ::: "memory");
}
__device__ __forceinline__ void cpa_wait1() {
    asm volatile("cp.async.wait_group 1;" ::: "memory");
}
__device__ __forceinline__ void cpa_wait0() {
    asm volatile("cp.async.wait_group 0;" ::: "memory");
}
__device__ __forceinline__ void mma8(float* c, const uint32_t* a,
                                     uint32_t b0, uint32_t b1) {
    asm volatile("mma.sync.aligned.m16n8k8.row.col.f32.tf32.tf32.f32 "
        "{%0,%1,%2,%3}, {%4,%5,%6,%7}, {%8,%9}, {%0,%1,%2,%3};"
        : "+f"(c[0]), "+f"(c[1]), "+f"(c[2]), "+f"(c[3])
        : "r"(a[0]), "r"(a[1]), "r"(a[2]), "r"(a[3]), "r"(b0), "r"(b1));
}

// ---------------- init: out = N * b1 (un-poisons d_out) ----------------
__global__ void tnep_init_kernel(float* __restrict__ out,
                                 const float* __restrict__ b1, int n) {
    out[0] = b1[0] * (float)n;
}

__global__ __launch_bounds__(NTHR, 1)
void tnep_mma(const float* __restrict__ q,
              const float* __restrict__ W0,
              const float* __restrict__ b0,
              const float* __restrict__ W1,
              const int*   __restrict__ Z,
              float* __restrict__ out,
              int n, int per)
{
    extern __shared__ char smc[];
    uint32_t* sW  = (uint32_t*)(smc + SW_OFF);   // raw fp32 weights, swizzled
    uint32_t* sQ  = (uint32_t*)(smc + SQ_OFF);   // Q chunk, original order, swizzled
    float* sB0 = (float*)(smc + B0_OFF);
    float* sW1 = (float*)(smc + W1_OFF);
    int* sIdx = (int*)(smc + IDX_OFF);           // LOCAL row index per sorted slot
    int* sZ   = (int*)(smc + SZ_OFF);
    int* hist = (int*)(smc + HIST_OFF);
    int* bse  = (int*)(smc + BASE_OFF);
    int* off  = (int*)(smc + OFF_OFF);
    int* tZ   = (int*)(smc + TZ_OFF);
    int* tS   = (int*)(smc + TS_OFF);
    int* tL   = (int*)(smc + TL_OFF);
    int* nT   = (int*)(smc + NT_OFF);

    const uint32_t smb = smem_u32(smc);
    const int tid  = threadIdx.x;
    const int wid  = tid >> 5;
    const int lane = tid & 31;

    const int s   = blockIdx.x * per;
    const int cnt = max(0, min(n - s, per));
    const int cnt_pad = (cnt + 31) & ~31;

    // ---- group 0: Z chunk (tiny, needed first for the sort) ----
    if (tid < cnt) cpa4(smb + SZ_OFF + tid * 4, Z + s + tid);
    cpa_commit();

    // ---- group 1: weights + biases + WHOLE Q chunk (original order) ----
    #pragma unroll
    for (int it = 0; it < 16; ++it) {                   // 8192 float4 / 512 thr
        const int i = tid + it * NTHR;
        const int t = i >> 10, j = i & 1023;
        const int d = j >> 4, n4 = j & 15;
        const uint32_t dst = smb + SW_OFF +
            (uint32_t)(t * 4096 + d * 64 + 4 * (n4 ^ (2 * (d & 7)))) * 4;
        cpa16(dst, (const float4*)W0 + i);
    }
    if (tid < 128) {
        cpa16(smb + B0_OFF + tid * 16, (const float4*)b0 + tid);
        cpa16(smb + W1_OFF + tid * 16, (const float4*)W1 + tid);
    }
    // Q rows 0..cnt_pad-1 (local order), dst col4 = sc4 ^ (r&7)
    for (int j = tid; j < cnt_pad * 16; j += NTHR) {
        const int r = j >> 4, sc4 = j & 15;
        const int gr = min(s + r, n - 1);               // clamp padding rows
        const uint32_t dst = smb + SQ_OFF +
            (uint32_t)(r * 64 + 4 * (sc4 ^ (r & 7))) * 4;
        cpa16(dst, q + (size_t)gr * 64 + 4 * sc4);
    }
    cpa_commit();

    for (int i = tid; i < 384; i += NTHR) sIdx[i] = 0;
    if (tid < NUM_TYPES) hist[tid] = 0;

    cpa_wait1();          // Z is resident; big group still flying
    __syncthreads();

    // ---- counting sort from smem Z (overlaps weight/Q arrival) ----
    for (int i = tid; i < cnt_pad; i += NTHR) {
        const bool v = (i < cnt);
        const int  z = v ? sZ[i] : -1;
        const unsigned m = __match_any_sync(0xffffffffu, z);
        if (v && (lane == (__ffs(m) - 1)))
            atomicAdd(&hist[z], __popc(m));
    }
    __syncthreads();
    if (tid == 0) {
        int acc = 0, nt = 0;
        #pragma unroll
        for (int t = 0; t < NUM_TYPES; ++t) { bse[t] = acc; off[t] = acc; acc += hist[t]; }
        for (int t = 0; t < NUM_TYPES; ++t) {           // M=16 tasks
            int c = hist[t], st = bse[t];
            while (c > 0 && nt < MAX_TASKS) {
                tZ[nt] = t; tS[nt] = st; tL[nt] = min(16, c);
                st += 16; c -= 16; ++nt;
            }
        }
        nT[0] = nt;
    }
    __syncthreads();
    for (int i = tid; i < cnt_pad; i += NTHR) {
        const bool v = (i < cnt);
        const int  z = v ? sZ[i] : -1;
        const unsigned m = __match_any_sync(0xffffffffu, z);
        const int leader = __ffs(m) - 1;
        const int rank   = __popc(m & ((1u << lane) - 1));
        int p0 = 0;
        if (v && lane == leader) p0 = atomicAdd(&off[z], __popc(m));
        p0 = __shfl_sync(0xffffffffu, p0, leader);
        if (v) sIdx[p0 + rank] = i;                     // local row index
    }

    cpa_wait0();          // weights + Q resident
    __syncthreads();

    // ---- MMA mainloop: one warp per 16-atom type-pure task ----
    const int ntasks = nT[0];
    const int g  = lane >> 2;       // 0..7
    const int t4 = lane & 3;        // 0..3
    float esum = 0.0f;

    for (int ti = wid; ti < ntasks; ti += NWARP) {
        const int z   = tZ[ti];
        const int ts  = tS[ti];
        const int len = tL[ti];

        // per-lane rows (indirect; padded slots -> row 0)
        const int r0 = sIdx[ts + g];
        const int r1 = sIdx[ts + g + 8];
        const uint32_t* p0r = sQ + r0 * 64;
        const uint32_t* p1r = sQ + r1 * 64;
        const int x0 = 4 * (r0 & 7);
        const int x1 = 4 * (r1 & 7);

        float C[8][4];
        #pragma unroll
        for (int i = 0; i < 8; ++i)
            #pragma unroll
            for (int j = 0; j < 4; ++j) C[i][j] = 0.0f;

        const uint32_t* wz = sW + z * 4096;

        #pragma unroll
        for (int kc = 0; kc < 8; ++kc) {
            const int k0 = 8 * kc + t4, k4 = k0 + 4;

            // A fragments: hi (rna tf32) + lo residual
            uint32_t ah[4], al[4];
            {
                const float v0 = __uint_as_float(p0r[k0 ^ x0]);
                const float v1 = __uint_as_float(p1r[k0 ^ x1]);
                const float v2 = __uint_as_float(p0r[k4 ^ x0]);
                const float v3 = __uint_as_float(p1r[k4 ^ x1]);
                ah[0] = f2tf(v0); al[0] = __float_as_uint(v0 - __uint_as_float(ah[0]));
                ah[1] = f2tf(v1); al[1] = __float_as_uint(v1 - __uint_as_float(ah[1]));
                ah[2] = f2tf(v2); al[2] = __float_as_uint(v2 - __uint_as_float(ah[2]));
                ah[3] = f2tf(v3); al[3] = __float_as_uint(v3 - __uint_as_float(ah[3]));
            }

            // B fragments: raw fp32 (HW tf32 truncation), conflict-free
            const int kb0 = k0, kb1 = k4;
            const uint32_t* wr0 = wz + kb0 * 64;
            const uint32_t* wr1 = wz + kb1 * 64;
            const int sx0 = 8 * (kb0 & 7);
            const int sx1 = 8 * (kb1 & 7);
            #pragma unroll
            for (int nt = 0; nt < 8; ++nt) {
                const int nn = 8 * nt + g;
                const uint32_t bf0 = wr0[nn ^ sx0];
                const uint32_t bf1 = wr1[nn ^ sx1];
                mma8(C[nt], ah, bf0, bf1);
                mma8(C[nt], al, bf0, bf1);
            }
        }

        // epilogue: bias + tanh + dot W1, mask padded rows
        const float* zb = sB0 + z * 64;
        const float* zw = sW1 + z * 64;
        const bool v0 = (g < len), v1 = (g + 8 < len);
        #pragma unroll
        for (int nt = 0; nt < 8; ++nt) {
            const int n0 = nt * 8 + 2 * t4, n1 = n0 + 1;
            const float bb0 = zb[n0], bb1 = zb[n1];
            const float ww0 = zw[n0], ww1 = zw[n1];
            if (v0) esum += fast_tanh(C[nt][0] + bb0) * ww0
                          + fast_tanh(C[nt][1] + bb1) * ww1;
            if (v1) esum += fast_tanh(C[nt][2] + bb0) * ww0
                          + fast_tanh(C[nt][3] + bb1) * ww1;
        }
    }

    // ---- reduce + one atomic per warp ----
    #pragma unroll
    for (int o = 16; o > 0; o >>= 1)
        esum += __shfl_xor_sync(0xffffffffu, esum, o);
    if (lane == 0)
        atomicAdd(out, esum);
}

extern "C" void kernel_launch(void* const* d_in, const int* in_sizes, int n_in,
                              void* d_out, int out_size) {
    // metadata order: descriptors, W0, b0, W1, b1, Z
    const float* q  = (const float*)d_in[0];
    const float* W0 = (const float*)d_in[1];
    const float* b0 = (const float*)d_in[2];
    const float* W1 = (const float*)d_in[3];
    const float* b1 = (const float*)d_in[4];
    const int*   Z  = (const int*)  d_in[5];
    float* out = (float*)d_out;

    const int n = in_sizes[5];            // N_ATOMS
    int per = (n + NBLK - 1) / NBLK;
    if (per > IDX_CAP) per = IDX_CAP;     // 148*352 = 52096 >= 50000

    cudaFuncSetAttribute(tnep_mma,
                         cudaFuncAttributeMaxDynamicSharedMemorySize,
                         SMEM_BYTES);

    tnep_init_kernel<<<1, 1>>>(out, b1, n);
    tnep_mma<<<NBLK, NTHR, SMEM_BYTES>>>(q, W0, b0, W1, Z, out, n, per);
}